// round 1
// baseline (speedup 1.0000x reference)
#include <cuda_runtime.h>
#include <cuda_bf16.h>

#define N_NODES  100000
#define N_EDGES  1600000
#define N_GRAPHS 64

// ---------------- scratch (device globals; no allocation allowed) ----------
__device__ __align__(256) float g_x1   [N_NODES * 8];   // n_feat * inv_sqrt_out
__device__ __align__(256) float g_agg1 [N_NODES * 8];
__device__ __align__(256) float g_h1s  [N_NODES * 16];  // relu(h1) * inv_sqrt_out
__device__ __align__(256) float g_agg2 [N_NODES * 16];
__device__ __align__(256) float g_z3   [N_NODES * 12];  // (h2*invout)@W3, stride 12 (10 used)
__device__ __align__(256) float g_agg3 [N_NODES * 12];
__device__ __align__(256) float g_invin [N_NODES];
__device__ __align__(256) float g_invout[N_NODES];
__device__ __align__(256) float g_degout[N_NODES];
__device__ __align__(256) float g_degin [N_NODES];
__device__ __align__(256) float g_gsum [N_GRAPHS * 10];

// ---------------- vector reductions (sm_90+) --------------------------------
__device__ __forceinline__ void red_add_v4(float* addr, float4 v) {
    asm volatile("red.global.add.v4.f32 [%0], {%1,%2,%3,%4};"
                 :: "l"(addr), "f"(v.x), "f"(v.y), "f"(v.z), "f"(v.w) : "memory");
}
__device__ __forceinline__ void red_add_v2(float* addr, float2 v) {
    asm volatile("red.global.add.v2.f32 [%0], {%1,%2};"
                 :: "l"(addr), "f"(v.x), "f"(v.y) : "memory");
}

// ---------------- kernels ----------------------------------------------------

// Zero all accumulators (1.6M threads covers the largest buffer)
__global__ void k_zero() {
    int i = blockIdx.x * blockDim.x + threadIdx.x;
    if (i < N_NODES * 8)   g_agg1[i] = 0.f;
    if (i < N_NODES * 16)  g_agg2[i] = 0.f;
    if (i < N_NODES * 12)  g_agg3[i] = 0.f;
    if (i < N_NODES)     { g_degout[i] = 0.f; g_degin[i] = 0.f; }
    if (i < N_GRAPHS * 10) g_gsum[i] = 0.f;
}

__global__ void k_degree(const int* __restrict__ src, const int* __restrict__ dst) {
    int e = blockIdx.x * blockDim.x + threadIdx.x;
    if (e < N_EDGES) {
        atomicAdd(&g_degout[src[e]], 1.f);
        atomicAdd(&g_degin [dst[e]], 1.f);
    }
}

// inv-sqrt degrees + pre-scale node features by inv_sqrt_out
__global__ void k_prep(const float* __restrict__ n_feat) {
    int i = blockIdx.x * blockDim.x + threadIdx.x;
    if (i >= N_NODES) return;
    float io = rsqrtf(fmaxf(g_degout[i], 1.f));
    float ii = rsqrtf(fmaxf(g_degin [i], 1.f));
    g_invout[i] = io;
    g_invin [i] = ii;
    const float4* xr = (const float4*)(n_feat + (size_t)i * 8);
    float4 a = xr[0], b = xr[1];
    a.x *= io; a.y *= io; a.z *= io; a.w *= io;
    b.x *= io; b.y *= io; b.z *= io; b.w *= io;
    float4* o = (float4*)(g_x1 + (size_t)i * 8);
    o[0] = a; o[1] = b;
}

// Layer 1 edge scatter: agg1[dst] += x1[src]   (8 floats)
__global__ void k_scatter1(const int* __restrict__ src, const int* __restrict__ dst) {
    int e = blockIdx.x * blockDim.x + threadIdx.x;
    if (e >= N_EDGES) return;
    int s = src[e], d = dst[e];
    const float4* xr = (const float4*)(g_x1 + (size_t)s * 8);
    float4 a = xr[0], b = xr[1];
    float* o = g_agg1 + (size_t)d * 8;
    red_add_v4(o,     a);
    red_add_v4(o + 4, b);
}

// Layer 1 dense: h1s = relu(agg1*invin @ W1 + b1) * invout    (8 -> 16)
__global__ void k_dense1(const float* __restrict__ W1, const float* __restrict__ b1) {
    __shared__ float sW[8 * 16];
    __shared__ float sb[16];
    int t = threadIdx.x;
    if (t < 128) sW[t] = W1[t];
    if (t < 16)  sb[t] = b1[t];
    __syncthreads();
    int i = blockIdx.x * blockDim.x + t;
    if (i >= N_NODES) return;
    float ii = g_invin[i], io = g_invout[i];
    const float4* ar = (const float4*)(g_agg1 + (size_t)i * 8);
    float4 p = ar[0], q = ar[1];
    float a[8] = {p.x*ii, p.y*ii, p.z*ii, p.w*ii, q.x*ii, q.y*ii, q.z*ii, q.w*ii};
    float acc[16];
    #pragma unroll
    for (int j = 0; j < 16; j++) acc[j] = sb[j];
    #pragma unroll
    for (int k = 0; k < 8; k++)
        #pragma unroll
        for (int j = 0; j < 16; j++)
            acc[j] = fmaf(a[k], sW[k * 16 + j], acc[j]);
    float4* o = (float4*)(g_h1s + (size_t)i * 16);
    #pragma unroll
    for (int v = 0; v < 4; v++) {
        float4 r;
        r.x = fmaxf(acc[v*4+0], 0.f) * io;
        r.y = fmaxf(acc[v*4+1], 0.f) * io;
        r.z = fmaxf(acc[v*4+2], 0.f) * io;
        r.w = fmaxf(acc[v*4+3], 0.f) * io;
        o[v] = r;
    }
}

// Layer 2 edge scatter: agg2[dst] += h1s[src]   (16 floats)
__global__ void k_scatter2(const int* __restrict__ src, const int* __restrict__ dst) {
    int e = blockIdx.x * blockDim.x + threadIdx.x;
    if (e >= N_EDGES) return;
    int s = src[e], d = dst[e];
    const float4* xr = (const float4*)(g_h1s + (size_t)s * 16);
    float4 a = xr[0], b = xr[1], c = xr[2], w = xr[3];
    float* o = g_agg2 + (size_t)d * 16;
    red_add_v4(o,      a);
    red_add_v4(o + 4,  b);
    red_add_v4(o + 8,  c);
    red_add_v4(o + 12, w);
}

// Layer 2 dense + layer 3 pre-matmul fused:
//   h2 = relu(agg2*invin @ W2 + b2)  (never materialized)
//   z3 = (h2 * invout) @ W3          (10 floats, stride 12)
__global__ void k_dense2(const float* __restrict__ W2, const float* __restrict__ b2,
                         const float* __restrict__ W3) {
    __shared__ float sW2[16 * 32];
    __shared__ float sb2[32];
    __shared__ float sW3[32 * 10];
    int t = threadIdx.x;
    for (int j = t; j < 16 * 32; j += blockDim.x) sW2[j] = W2[j];
    for (int j = t; j < 32 * 10; j += blockDim.x) sW3[j] = W3[j];
    if (t < 32) sb2[t] = b2[t];
    __syncthreads();
    int i = blockIdx.x * blockDim.x + t;
    if (i >= N_NODES) return;
    float ii = g_invin[i], io = g_invout[i];
    float a[16];
    const float4* ar = (const float4*)(g_agg2 + (size_t)i * 16);
    #pragma unroll
    for (int v = 0; v < 4; v++) {
        float4 p = ar[v];
        a[v*4+0] = p.x*ii; a[v*4+1] = p.y*ii; a[v*4+2] = p.z*ii; a[v*4+3] = p.w*ii;
    }
    float acc[32];
    #pragma unroll
    for (int j = 0; j < 32; j++) acc[j] = sb2[j];
    #pragma unroll
    for (int k = 0; k < 16; k++)
        #pragma unroll
        for (int j = 0; j < 32; j++)
            acc[j] = fmaf(a[k], sW2[k * 32 + j], acc[j]);
    float z[10];
    #pragma unroll
    for (int j = 0; j < 10; j++) z[j] = 0.f;
    #pragma unroll
    for (int k = 0; k < 32; k++) {
        float h = fmaxf(acc[k], 0.f) * io;
        #pragma unroll
        for (int j = 0; j < 10; j++)
            z[j] = fmaf(h, sW3[k * 10 + j], z[j]);
    }
    float* o = g_z3 + (size_t)i * 12;
    *(float4*)(o)     = make_float4(z[0], z[1], z[2], z[3]);
    *(float4*)(o + 4) = make_float4(z[4], z[5], z[6], z[7]);
    *(float2*)(o + 8) = make_float2(z[8], z[9]);
}

// Layer 3 edge scatter: agg3[dst] += z3[src]    (10 floats, stride 12)
__global__ void k_scatter3(const int* __restrict__ src, const int* __restrict__ dst) {
    int e = blockIdx.x * blockDim.x + threadIdx.x;
    if (e >= N_EDGES) return;
    int s = src[e], d = dst[e];
    const float* xr = g_z3 + (size_t)s * 12;
    float4 a = *(const float4*)(xr);
    float4 b = *(const float4*)(xr + 4);
    float2 c = *(const float2*)(xr + 8);
    float* o = g_agg3 + (size_t)d * 12;
    red_add_v4(o,     a);
    red_add_v4(o + 4, b);
    red_add_v2(o + 8, c);
}

// Per-graph sum pooling (graph_ids sorted -> shared-mem accumulate, skip-zero flush)
__global__ void k_pool(const int* __restrict__ gids) {
    __shared__ float ssum[N_GRAPHS * 10];
    int t = threadIdx.x;
    for (int j = t; j < N_GRAPHS * 10; j += blockDim.x) ssum[j] = 0.f;
    __syncthreads();
    int i = blockIdx.x * blockDim.x + t;
    if (i < N_NODES) {
        int g = gids[i];
        float ii = g_invin[i];
        const float* r = g_agg3 + (size_t)i * 12;
        #pragma unroll
        for (int j = 0; j < 10; j++)
            atomicAdd(&ssum[g * 10 + j], r[j] * ii);
    }
    __syncthreads();
    for (int j = t; j < N_GRAPHS * 10; j += blockDim.x) {
        float v = ssum[j];
        if (v != 0.f) atomicAdd(&g_gsum[j], v);
    }
}

__device__ __forceinline__ int lowerb(const int* __restrict__ a, int n, int v) {
    int lo = 0, hi = n;
    while (lo < hi) {
        int m = (lo + hi) >> 1;
        if (a[m] < v) lo = m + 1; else hi = m;
    }
    return lo;
}

// Finalize: out[g][j] = gsum[g][j] / max(count_g,1) + b3[j]
// counts via binary search on sorted graph_ids (no atomics)
__global__ void k_final(const int* __restrict__ gids, const float* __restrict__ b3,
                        float* __restrict__ out) {
    int i = blockIdx.x * blockDim.x + threadIdx.x;
    if (i >= N_GRAPHS * 10) return;
    int g = i / 10, j = i % 10;
    int lo = lowerb(gids, N_NODES, g);
    int hi = lowerb(gids, N_NODES, g + 1);
    float cnt = (float)(hi - lo);
    out[i] = g_gsum[i] / fmaxf(cnt, 1.f) + b3[j];
}

// ---------------- launch ------------------------------------------------------
extern "C" void kernel_launch(void* const* d_in, const int* in_sizes, int n_in,
                              void* d_out, int out_size) {
    const float* n_feat = (const float*)d_in[0];
    const int*   src    = (const int*)  d_in[1];
    const int*   dst    = (const int*)  d_in[2];
    const int*   gids   = (const int*)  d_in[3];
    const float* W1     = (const float*)d_in[4];
    const float* b1     = (const float*)d_in[5];
    const float* W2     = (const float*)d_in[6];
    const float* b2     = (const float*)d_in[7];
    const float* W3     = (const float*)d_in[8];
    const float* b3     = (const float*)d_in[9];
    float* out = (float*)d_out;

    const int TB = 256;
    const int eb = (N_EDGES + TB - 1) / TB;          // 6250
    const int nb = (N_NODES + TB - 1) / TB;          // 391
    const int zb = (N_NODES * 16 + TB - 1) / TB;     // covers largest buffer

    k_zero    <<<zb, TB>>>();
    k_degree  <<<eb, TB>>>(src, dst);
    k_prep    <<<nb, TB>>>(n_feat);
    k_scatter1<<<eb, TB>>>(src, dst);
    k_dense1  <<<nb, TB>>>(W1, b1);
    k_scatter2<<<eb, TB>>>(src, dst);
    k_dense2  <<<nb, TB>>>(W2, b2, W3);
    k_scatter3<<<eb, TB>>>(src, dst);
    k_pool    <<<nb, TB>>>(gids);
    k_final   <<<(N_GRAPHS * 10 + TB - 1) / TB, TB>>>(gids, b3, out);
}